// round 15
// baseline (speedup 1.0000x reference)
#include <cuda_runtime.h>
#include <cuda_bf16.h>
#include <cstdint>

// ---------------- problem constants ----------------
#define T_    256
#define B_    128
#define E_    1024
#define H_    1024
#define N4_   4096
#define BH_   (B_ * H_)
#define NSPLIT 4

// ---------------- static device scratch ----------------
// weights / z use GATE-INTERLEAVED column order: col' = 4*unit + gate
__device__ float          g_zx[(size_t)T_ * B_ * N4_];   // x-part preactivations (interleaved)
__device__ float          g_zh[NSPLIT * B_ * N4_];       // per-step h-part partials
__device__ float4         g_b4[H_];                      // interleaved bias {bg,bi,bf,bo}[u]
__device__ __nv_bfloat16  g_eh[(size_t)T_ * B_ * E_];    // embeds hi
__device__ __nv_bfloat16  g_el[(size_t)T_ * B_ * E_];    // embeds lo
__device__ __nv_bfloat16  g_wxh[N4_ * 1024];             // Wx hi (interleaved rows, K-major)
__device__ __nv_bfloat16  g_wxl[N4_ * 1024];
__device__ __nv_bfloat16  g_whh[N4_ * 1024];             // Wh hi (interleaved rows)
__device__ __nv_bfloat16  g_whl[N4_ * 1024];
__device__ __nv_bfloat16  g_hh[3][BH_];                  // h triple buffer, hi plane
__device__ __nv_bfloat16  g_hl[3][BH_];                  // h triple buffer, lo plane
__device__ unsigned       g_hcnt[4];                     // per-region h-ready counters (monotonic)
__device__ unsigned       g_pcnt[32];                    // per-nt partial counters (monotonic)
__device__ unsigned       g_zxcnt[T_];                   // per-step zx-tile counters (monotonic)

// ---------------- arch-generic PTX helpers ----------------
__device__ __forceinline__ uint32_t smem_u32(const void* p) {
    uint32_t a;
    asm("{ .reg .u64 t; cvta.to.shared.u64 t, %1; cvt.u32.u64 %0, t; }" : "=r"(a) : "l"(p));
    return a;
}
__device__ __forceinline__ void ldsm4(uint32_t r[4], uint32_t saddr) {
    asm volatile("ldmatrix.sync.aligned.m8n8.x4.shared.b16 {%0,%1,%2,%3}, [%4];"
                 : "=r"(r[0]), "=r"(r[1]), "=r"(r[2]), "=r"(r[3]) : "r"(saddr));
}
__device__ __forceinline__ void mma16816(float c[4], const uint32_t a[4],
                                         uint32_t b0, uint32_t b1) {
    asm volatile("mma.sync.aligned.m16n8k16.row.col.f32.bf16.bf16.f32 "
                 "{%0,%1,%2,%3}, {%4,%5,%6,%7}, {%8,%9}, {%0,%1,%2,%3};"
                 : "+f"(c[0]), "+f"(c[1]), "+f"(c[2]), "+f"(c[3])
                 : "r"(a[0]), "r"(a[1]), "r"(a[2]), "r"(a[3]), "r"(b0), "r"(b1));
}
#define CP_ASYNC16(dst, src) \
    asm volatile("cp.async.cg.shared.global [%0], [%1], 16;" :: "r"(dst), "l"(src))
#define CP_COMMIT() asm volatile("cp.async.commit_group;" ::: "memory")
#define CP_WAIT0()  asm volatile("cp.async.wait_group 0;" ::: "memory")
#define CP_WAIT1()  asm volatile("cp.async.wait_group 1;" ::: "memory")

// fast sigmoid/tanh via MUFU exp (rel err ~1e-7; within precision budget)
__device__ __forceinline__ float fsig(float x)  { return 1.0f / (1.0f + __expf(-x)); }
__device__ __forceinline__ float ftanh(float x) { return 2.0f / (1.0f + __expf(-2.0f * x)) - 1.0f; }

// ---------------- fused persistent kernel ----------------
// Grid = 148 CTAs x 512 threads, 1 CTA/SM (224KB smem), all co-resident.
//   CTA 0..127  : recurrence, CTA = (nt 0..31, kz 0..3), R11 region-flag scheme.
//   CTA 128..147: zx workers — stream Zx tiles (mt 1..255, 32 nt each) in the
//                 background, signaling g_zxcnt[mt]; recurrence eltwise waits.
#define PK_CTAS    148
#define PK_WORKERS 20
#define PK_THREADS 512
#define SM_WHI(s)   (sm + (s) * 16384)
#define SM_WLO(s)   (sm + 65536 + (s) * 16384)
#define SM_HBUF(b)  (sm + 131072 + (b) * 32768)
#define PK_SMEM     (131072 + 3 * 32768)      // 229376

__global__ __launch_bounds__(PK_THREADS, 1)
void lstm_persistent(float* __restrict__ out)
{
    extern __shared__ __align__(128) char sm[];

    const int tid  = threadIdx.x;
    const int lane = tid & 31;
    const int wid  = tid >> 5;
    const int wm   = wid & 3;        // 4 warp-rows of 32 m
    const int wn   = wid >> 2;       // 4 warp-cols of 32 n
    const int cta  = blockIdx.x;

    if (cta >= 128) {
        // ================= zx worker path =================
        const int w = cta - 128;

#define WLOAD_STAGE(buf, s) do {                                                    \
            char* dst_ = sm + (buf) * 65536;                                        \
            _Pragma("unroll")                                                       \
            for (int i = 0; i < 8; ++i) {                                           \
                int c_ = tid + i * 512;                                             \
                int tl_ = c_ >> 10, rm_ = c_ & 1023, row_ = rm_ >> 3, c8_ = rm_ & 7;\
                const __nv_bfloat16* base_ =                                        \
                    (tl_ == 0) ? a_h : (tl_ == 1) ? a_l : (tl_ == 2) ? b_h : b_l;   \
                uint32_t so_ = tl_ * 16384 + row_ * 128 + ((c8_ ^ (row_ & 7)) << 4);\
                CP_ASYNC16(smem_u32(dst_ + so_),                                    \
                           base_ + (size_t)row_ * 1024 + (s) * 64 + c8_ * 8);       \
            }                                                                       \
            CP_COMMIT();                                                            \
        } while (0)

#pragma unroll 1
        for (int idx = 32 + w; idx < 8192; idx += PK_WORKERS) {
            const int mt  = idx >> 5;      // step t (1..255)
            const int ntw = idx & 31;      // n-tile
            const __nv_bfloat16* a_h = g_eh + (size_t)mt * 128 * 1024;
            const __nv_bfloat16* a_l = g_el + (size_t)mt * 128 * 1024;
            const __nv_bfloat16* b_h = g_wxh + (size_t)ntw * 128 * 1024;
            const __nv_bfloat16* b_l = g_wxl + (size_t)ntw * 128 * 1024;

            float cacc[2][4][4];
#pragma unroll
            for (int mi = 0; mi < 2; ++mi)
#pragma unroll
                for (int ni = 0; ni < 4; ++ni)
#pragma unroll
                    for (int q = 0; q < 4; ++q) cacc[mi][ni][q] = 0.0f;

            WLOAD_STAGE(0, 0);
            WLOAD_STAGE(1, 1);

#pragma unroll 1
            for (int s = 0; s < 16; ++s) {
                if (s + 1 < 16) { CP_WAIT1(); } else { CP_WAIT0(); }
                __syncthreads();

                const char* base = sm + (s % 3) * 65536;
#pragma unroll
                for (int j = 0; j < 4; ++j) {
                    uint32_t aH[2][4], aL[2][4], bH[2][4], bL[2][4];
#pragma unroll
                    for (int mi = 0; mi < 2; ++mi) {
                        int row = wm * 32 + mi * 16 + (lane & 15);
                        int ch  = 2 * j + (lane >> 4);
                        uint32_t off = row * 128 + ((ch ^ (row & 7)) << 4);
                        ldsm4(aH[mi], smem_u32(base + 0     + off));
                        ldsm4(aL[mi], smem_u32(base + 16384 + off));
                    }
#pragma unroll
                    for (int pi = 0; pi < 2; ++pi) {
                        int row = wn * 32 + pi * 16 + (lane & 7) + ((lane & 16) >> 1);
                        int ch  = 2 * j + ((lane >> 3) & 1);
                        uint32_t off = row * 128 + ((ch ^ (row & 7)) << 4);
                        ldsm4(bH[pi], smem_u32(base + 32768 + off));
                        ldsm4(bL[pi], smem_u32(base + 49152 + off));
                    }
#pragma unroll
                    for (int mi = 0; mi < 2; ++mi)
#pragma unroll
                        for (int ni = 0; ni < 4; ++ni) {
                            uint32_t bh0 = bH[ni >> 1][(ni & 1) * 2];
                            uint32_t bh1 = bH[ni >> 1][(ni & 1) * 2 + 1];
                            uint32_t bl0 = bL[ni >> 1][(ni & 1) * 2];
                            uint32_t bl1 = bL[ni >> 1][(ni & 1) * 2 + 1];
                            mma16816(cacc[mi][ni], aH[mi], bh0, bh1);
                            mma16816(cacc[mi][ni], aH[mi], bl0, bl1);
                            mma16816(cacc[mi][ni], aL[mi], bh0, bh1);
                        }
                }
                // 3-buffer rotation: buffer (s+2)%3 was read at stage s-1; all
                // threads passed the stage-s sync since -> safe to refill.
                if (s + 2 < 16) WLOAD_STAGE((s + 2) % 3, s + 2);
            }

            // epilogue -> g_zx, then signal
            {
                float* cb = g_zx + (size_t)mt * 128 * N4_ + ntw * 128;
#pragma unroll
                for (int mi = 0; mi < 2; ++mi)
#pragma unroll
                    for (int ni = 0; ni < 4; ++ni) {
                        int r   = wm * 32 + mi * 16 + (lane >> 2);
                        int col = wn * 32 + ni * 8 + (lane & 3) * 2;
                        *(float2*)(cb + (size_t)r * N4_ + col) =
                            make_float2(cacc[mi][ni][0], cacc[mi][ni][1]);
                        *(float2*)(cb + (size_t)(r + 8) * N4_ + col) =
                            make_float2(cacc[mi][ni][2], cacc[mi][ni][3]);
                    }
            }
            __threadfence();                 // release (all threads)
            __syncthreads();
            if (tid == 0) atomicAdd(&g_zxcnt[mt], 1u);
        }
#undef WLOAD_STAGE
        return;
    }

    // ================= recurrence path (R11 structure) =================
    const int nt   = cta & 31;
    const int kz   = cta >> 5;
    const int reg_own = nt >> 3;     // region this CTA's h output belongs to

    // eltwise ownership: rows kz*32 + b_r, unit-pair uh
    const int b_r = tid >> 4;
    const int uh  = tid & 15;
    const int gr  = kz * 32 + b_r;
    const int u0  = nt * 32 + uh * 2;

    float c0 = 0.0f, c1 = 0.0f;      // resident cell state

    // ---- resident W slab: 4 K64 sub-slabs, hi+lo ----
#pragma unroll
    for (int sub = 0; sub < 4; ++sub) {
#pragma unroll
        for (int i = 0; i < 4; ++i) {
            int c_ = tid + i * 512;
            int pl = c_ >> 10, rm = c_ & 1023, row = rm >> 3, c8 = rm & 7;
            const __nv_bfloat16* src = (pl ? g_whl : g_whh) +
                (size_t)(nt * 128 + row) * 1024 + kz * 256 + sub * 64 + c8 * 8;
            uint32_t so = row * 128 + ((c8 ^ (row & 7)) << 4);
            CP_ASYNC16(smem_u32((pl ? SM_WLO(sub) : SM_WHI(sub)) + so), src);
        }
    }
    CP_COMMIT();

#define LOADH(buf, s, rp) do {                                                      \
        char* dst_ = SM_HBUF(buf);                                                  \
        const __nv_bfloat16* hh_ = g_hh[rp];                                        \
        const __nv_bfloat16* hl_ = g_hl[rp];                                        \
        _Pragma("unroll")                                                           \
        for (int i = 0; i < 4; ++i) {                                               \
            int c_ = tid + i * 512;                                                 \
            int pl_ = c_ >> 10, rm_ = c_ & 1023, row_ = rm_ >> 3, c8_ = rm_ & 7;    \
            const __nv_bfloat16* src_ = (pl_ ? hl_ : hh_) +                         \
                (size_t)row_ * 1024 + kz * 256 + (s) * 64 + c8_ * 8;                \
            uint32_t so_ = pl_ * 16384 + row_ * 128 + ((c8_ ^ (row_ & 7)) << 4);    \
            CP_ASYNC16(smem_u32(dst_ + so_), src_);                                 \
        }                                                                           \
        CP_COMMIT();                                                                \
    } while (0)

#pragma unroll 1
    for (int t = 1; t < T_; ++t) {
        // wait: region kz h-ready (GEMM input) + own region (slot-reuse safety)
        if (tid == 0) {
            unsigned tgt = 32u * (unsigned)(t - 1);
            while (*(volatile unsigned*)&g_hcnt[kz] < tgt) { }
            if (reg_own != kz)
                while (*(volatile unsigned*)&g_hcnt[reg_own] < tgt) { }
            __threadfence();     // acquire
        }
        __syncthreads();

        const int rp = (t - 1) % 3;
        const int wp = t % 3;

        LOADH(0, 0, rp);
        LOADH(1, 1, rp);

        float cacc[2][4][4];
#pragma unroll
        for (int mi = 0; mi < 2; ++mi)
#pragma unroll
            for (int ni = 0; ni < 4; ++ni)
#pragma unroll
                for (int q = 0; q < 4; ++q) cacc[mi][ni][q] = 0.0f;

#pragma unroll 1
        for (int s = 0; s < 4; ++s) {
            if (s < 3) { CP_WAIT1(); } else { CP_WAIT0(); }
            __syncthreads();

            const char* abase  = SM_HBUF(s % 3);
            const char* bhbase = SM_WHI(s);
            const char* blbase = SM_WLO(s);
#pragma unroll
            for (int j = 0; j < 4; ++j) {
                uint32_t aH[2][4], aL[2][4], bH[2][4], bL[2][4];
#pragma unroll
                for (int mi = 0; mi < 2; ++mi) {
                    int row = wm * 32 + mi * 16 + (lane & 15);
                    int ch  = 2 * j + (lane >> 4);
                    uint32_t off = row * 128 + ((ch ^ (row & 7)) << 4);
                    ldsm4(aH[mi], smem_u32(abase + off));
                    ldsm4(aL[mi], smem_u32(abase + 16384 + off));
                }
#pragma unroll
                for (int pi = 0; pi < 2; ++pi) {
                    int row = wn * 32 + pi * 16 + (lane & 7) + ((lane & 16) >> 1);
                    int ch  = 2 * j + ((lane >> 3) & 1);
                    uint32_t off = row * 128 + ((ch ^ (row & 7)) << 4);
                    ldsm4(bH[pi], smem_u32(bhbase + off));
                    ldsm4(bL[pi], smem_u32(blbase + off));
                }
#pragma unroll
                for (int mi = 0; mi < 2; ++mi)
#pragma unroll
                    for (int ni = 0; ni < 4; ++ni) {
                        uint32_t bh0 = bH[ni >> 1][(ni & 1) * 2];
                        uint32_t bh1 = bH[ni >> 1][(ni & 1) * 2 + 1];
                        uint32_t bl0 = bL[ni >> 1][(ni & 1) * 2];
                        uint32_t bl1 = bL[ni >> 1][(ni & 1) * 2 + 1];
                        mma16816(cacc[mi][ni], aH[mi], bh0, bh1);
                        mma16816(cacc[mi][ni], aH[mi], bl0, bl1);
                        mma16816(cacc[mi][ni], aL[mi], bh0, bh1);
                    }
            }
            if (s + 2 < 4) LOADH((s + 2) % 3, s + 2, rp);
        }

        // ---- write z partials ----
        {
            float* cb = g_zh + (size_t)kz * (B_ * N4_) + nt * 128;
#pragma unroll
            for (int mi = 0; mi < 2; ++mi)
#pragma unroll
                for (int ni = 0; ni < 4; ++ni) {
                    int r   = wm * 32 + mi * 16 + (lane >> 2);
                    int col = wn * 32 + ni * 8 + (lane & 3) * 2;
                    *(float2*)(cb + (size_t)r * N4_ + col) =
                        make_float2(cacc[mi][ni][0], cacc[mi][ni][1]);
                    *(float2*)(cb + (size_t)(r + 8) * N4_ + col) =
                        make_float2(cacc[mi][ni][2], cacc[mi][ni][3]);
                }
        }
        __syncthreads();
        if (tid == 0) {
            __threadfence();                       // release partials
            atomicAdd(&g_pcnt[nt], 1u);
            unsigned tgt = 4u * (unsigned)t;
            while (*(volatile unsigned*)&g_pcnt[nt] < tgt) { }
            // zx tile for this step must be produced by the workers
            while (*(volatile unsigned*)&g_zxcnt[t] < 32u) { }
            __threadfence();                       // acquire partials + zx
        }
        __syncthreads();

        // ---- local eltwise: rows kz*32.., this nt's 32 units ----
        float hv0, hv1;
        {
            size_t rowoff = (size_t)gr * N4_ + nt * 128 + uh * 8;
            const float4* px = (const float4*)(g_zx + (size_t)t * B_ * N4_ + rowoff);
            float4 z0 = __ldg(px + 0);
            float4 z1 = __ldg(px + 1);
#pragma unroll
            for (int kzi = 0; kzi < NSPLIT; ++kzi) {
                const float4* pp = (const float4*)(g_zh + (size_t)kzi * (B_ * N4_) + rowoff);
                float4 a0 = __ldcg(pp + 0), a1 = __ldcg(pp + 1);
                z0.x += a0.x; z0.y += a0.y; z0.z += a0.z; z0.w += a0.w;
                z1.x += a1.x; z1.y += a1.y; z1.z += a1.z; z1.w += a1.w;
            }
            float4 bb0 = g_b4[u0];
            float4 bb1 = g_b4[u0 + 1];
            {
                float g  = ftanh(z0.x + bb0.x);
                float ii = fsig(z0.y + bb0.y);
                float f  = fsig(z0.z + bb0.z);
                float o  = fsig(z0.w + bb0.w);
                c0 = f * c0 + ii * g;
                hv0 = o * ftanh(c0);
            }
            {
                float g  = ftanh(z1.x + bb1.x);
                float ii = fsig(z1.y + bb1.y);
                float f  = fsig(z1.z + bb1.z);
                float o  = fsig(z1.w + bb1.w);
                c1 = f * c1 + ii * g;
                hv1 = o * ftanh(c1);
            }

            union { __nv_bfloat16 v[2]; uint32_t u; } hh, hl;
            __nv_bfloat16 h0 = __float2bfloat16(hv0);
            __nv_bfloat16 h1 = __float2bfloat16(hv1);
            hh.v[0] = h0; hh.v[1] = h1;
            hl.v[0] = __float2bfloat16(hv0 - __bfloat162float(h0));
            hl.v[1] = __float2bfloat16(hv1 - __bfloat162float(h1));
            *(uint32_t*)(g_hh[wp] + (size_t)gr * 1024 + u0) = hh.u;
            *(uint32_t*)(g_hl[wp] + (size_t)gr * 1024 + u0) = hl.u;
        }
        __syncthreads();
        if (tid == 0) {
            __threadfence();                       // release h planes
            atomicAdd(&g_hcnt[reg_own], 1u);       // h region ready
        }
        // out store off the critical path (device never reads out)
        *(float2*)(out + ((size_t)t * B_ + gr) * 1024 + u0) = make_float2(hv0, hv1);
    }
#undef LOADH
}

// ---------------- prep kernels ----------------
__global__ void split_plane(const float* __restrict__ src, __nv_bfloat16* __restrict__ hi,
                            __nv_bfloat16* __restrict__ lo, int n) {
    int i = blockIdx.x * blockDim.x + threadIdx.x;
    if (i < n) {
        float v = src[i];
        __nv_bfloat16 h = __float2bfloat16(v);
        hi[i] = h;
        lo[i] = __float2bfloat16(v - __bfloat162float(h));
    }
}

// gate-INTERLEAVED weight split: dest row = 4*unit + gate
__global__ void split_W(const float* __restrict__ Wg, const float* __restrict__ Wi,
                        const float* __restrict__ Wf, const float* __restrict__ Wo) {
    int idx = blockIdx.x * blockDim.x + threadIdx.x;
    if (idx >= 4 * 1024 * 2048) return;
    int gate = idx >> 21;
    int rem  = idx & ((1 << 21) - 1);
    int n    = rem >> 11;
    int k    = rem & 2047;
    const float* W = (gate == 0) ? Wg : (gate == 1) ? Wi : (gate == 2) ? Wf : Wo;
    float v = W[(size_t)n * 2048 + k];
    __nv_bfloat16 h = __float2bfloat16(v);
    __nv_bfloat16 l = __float2bfloat16(v - __bfloat162float(h));
    int gr = 4 * n + gate;
    if (k < 1024) {
        g_wxh[(size_t)gr * 1024 + k] = h;
        g_wxl[(size_t)gr * 1024 + k] = l;
    } else {
        g_whh[(size_t)gr * 1024 + (k - 1024)] = h;
        g_whl[(size_t)gr * 1024 + (k - 1024)] = l;
    }
}

__global__ void init_state(float* __restrict__ out,
                           const float* __restrict__ bg, const float* __restrict__ bi,
                           const float* __restrict__ bf, const float* __restrict__ bo) {
    int i = blockIdx.x * blockDim.x + threadIdx.x;
    if (i < BH_) {
        out[i] = 0.0f;                          // output[0] = h0 = 0
        g_hh[0][i] = __float2bfloat16(0.0f);    // h_0 planes (rp of t=1 is buffer 0)
        g_hl[0][i] = __float2bfloat16(0.0f);
    }
    if (i < H_) g_b4[i] = make_float4(bg[i], bi[i], bf[i], bo[i]);
    if (i < 32) g_pcnt[i] = 0;
    if (i < 4)  g_hcnt[i] = 0;
    if (i < T_) g_zxcnt[i] = 0;
}

// ---------------- launch ----------------
extern "C" void kernel_launch(void* const* d_in, const int* in_sizes, int n_in,
                              void* d_out, int out_size)
{
    const float* embeds = (const float*)d_in[0];
    const float* Wg = (const float*)d_in[1];
    const float* Wi = (const float*)d_in[2];
    const float* Wf = (const float*)d_in[3];
    const float* Wo = (const float*)d_in[4];
    const float* bg = (const float*)d_in[5];
    const float* bi = (const float*)d_in[6];
    const float* bf = (const float*)d_in[7];
    const float* bo = (const float*)d_in[8];
    float* out = (float*)d_out;

    cudaFuncSetAttribute(lstm_persistent, cudaFuncAttributeMaxDynamicSharedMemorySize, PK_SMEM);

    __nv_bfloat16 *p_eh, *p_el;
    cudaGetSymbolAddress((void**)&p_eh,  g_eh);
    cudaGetSymbolAddress((void**)&p_el,  g_el);

    // prep
    {
        int n = T_ * B_ * E_;
        split_plane<<<(n + 255) / 256, 256>>>(embeds, p_eh, p_el, n);
    }
    split_W<<<(4 * 1024 * 2048 + 255) / 256, 256>>>(Wg, Wi, Wf, Wo);
    init_state<<<(BH_ + 255) / 256, 256>>>(out, bg, bi, bf, bo);

    // one fused persistent kernel: 128 recurrence CTAs + 20 zx-worker CTAs
    lstm_persistent<<<PK_CTAS, PK_THREADS, PK_SMEM>>>(out);
}

// round 16
// speedup vs baseline: 1.7810x; 1.7810x over previous
#include <cuda_runtime.h>
#include <cuda_bf16.h>
#include <cstdint>

// ---------------- problem constants ----------------
#define T_    256
#define B_    128
#define E_    1024
#define H_    1024
#define N4_   4096
#define BH_   (B_ * H_)
#define NSPLIT 4

// ---------------- static device scratch ----------------
// weights / z use GATE-INTERLEAVED column order: col' = 4*unit + gate
__device__ float          g_zx[(size_t)T_ * B_ * N4_];   // x-part preactivations (interleaved)
__device__ float          g_zh[NSPLIT * B_ * N4_];       // per-step h-part partials
__device__ float4         g_b4[H_];                      // interleaved bias {bg,bi,bf,bo}[u]
__device__ __nv_bfloat16  g_eh[(size_t)T_ * B_ * E_];    // embeds hi
__device__ __nv_bfloat16  g_el[(size_t)T_ * B_ * E_];    // embeds lo
__device__ __nv_bfloat16  g_wxh[N4_ * 1024];             // Wx hi (interleaved rows, K-major)
__device__ __nv_bfloat16  g_wxl[N4_ * 1024];
__device__ __nv_bfloat16  g_whh[N4_ * 1024];             // Wh hi (interleaved rows)
__device__ __nv_bfloat16  g_whl[N4_ * 1024];
__device__ __nv_bfloat16  g_hh[3][BH_];                  // h triple buffer, hi plane
__device__ __nv_bfloat16  g_hl[3][BH_];                  // h triple buffer, lo plane
__device__ unsigned       g_hnt[32];                     // per-nt h-ready counters (monotonic)
__device__ unsigned       g_pcnt[32];                    // per-nt partial counters (monotonic)

// ---------------- arch-generic PTX helpers ----------------
__device__ __forceinline__ uint32_t smem_u32(const void* p) {
    uint32_t a;
    asm("{ .reg .u64 t; cvta.to.shared.u64 t, %1; cvt.u32.u64 %0, t; }" : "=r"(a) : "l"(p));
    return a;
}
__device__ __forceinline__ void ldsm4(uint32_t r[4], uint32_t saddr) {
    asm volatile("ldmatrix.sync.aligned.m8n8.x4.shared.b16 {%0,%1,%2,%3}, [%4];"
                 : "=r"(r[0]), "=r"(r[1]), "=r"(r[2]), "=r"(r[3]) : "r"(saddr));
}
__device__ __forceinline__ void mma16816(float c[4], const uint32_t a[4],
                                         uint32_t b0, uint32_t b1) {
    asm volatile("mma.sync.aligned.m16n8k16.row.col.f32.bf16.bf16.f32 "
                 "{%0,%1,%2,%3}, {%4,%5,%6,%7}, {%8,%9}, {%0,%1,%2,%3};"
                 : "+f"(c[0]), "+f"(c[1]), "+f"(c[2]), "+f"(c[3])
                 : "r"(a[0]), "r"(a[1]), "r"(a[2]), "r"(a[3]), "r"(b0), "r"(b1));
}
#define CP_ASYNC16(dst, src) \
    asm volatile("cp.async.cg.shared.global [%0], [%1], 16;" :: "r"(dst), "l"(src))
#define CP_COMMIT() asm volatile("cp.async.commit_group;" ::: "memory")
#define CP_WAIT0()  asm volatile("cp.async.wait_group 0;" ::: "memory")
#define CP_WAIT1()  asm volatile("cp.async.wait_group 1;" ::: "memory")

// fast sigmoid/tanh via MUFU exp (rel err ~1e-7; within precision budget)
__device__ __forceinline__ float fsig(float x)  { return 1.0f / (1.0f + __expf(-x)); }
__device__ __forceinline__ float ftanh(float x) { return 2.0f / (1.0f + __expf(-2.0f * x)) - 1.0f; }

// polite monotonic-counter wait: one check, then nanosleep backoff (no L2 storm)
#define WAIT_CNT(arr, idx, tgt) do {                                                \
        if (*(volatile unsigned*)&(arr)[idx] < (tgt)) {                             \
            do { __nanosleep(200); }                                                \
            while (*(volatile unsigned*)&(arr)[idx] < (tgt));                       \
        }                                                                           \
    } while (0)

// ---------------- batch 3-plane bf16 GEMM (3-stage pipeline, known-good) ----------------
__global__ __launch_bounds__(256, 1)
void gemm_mma(const __nv_bfloat16* __restrict__ Ah, const __nv_bfloat16* __restrict__ Al,
              int lda,
              const __nv_bfloat16* __restrict__ Bh, const __nv_bfloat16* __restrict__ Bl,
              float* __restrict__ C, size_t csplit_stride, int klen)
{
    extern __shared__ __align__(128) char sm[];

    const int tid  = threadIdx.x;
    const int lane = tid & 31;
    const int wid  = tid >> 5;
    const int wm   = wid & 1;
    const int wn   = wid >> 1;
    const int nt = blockIdx.x, mt = blockIdx.y, kz = blockIdx.z;
    const int kofs = kz * klen;
    const int nstages = klen >> 6;

    const __nv_bfloat16* a_h = Ah + (size_t)mt * 128 * lda + kofs;
    const __nv_bfloat16* a_l = Al + (size_t)mt * 128 * lda + kofs;
    const __nv_bfloat16* b_h = Bh + (size_t)nt * 128 * 1024 + kofs;
    const __nv_bfloat16* b_l = Bl + (size_t)nt * 128 * 1024 + kofs;

    const int lrow = tid >> 3;
    const int lc   = tid & 7;

#define LOAD_STAGE(buf, s) do {                                                    \
        char* dst_ = sm + (buf) * 65536;                                           \
        const __nv_bfloat16* s0_ = a_h + (s) * 64;                                 \
        const __nv_bfloat16* s1_ = a_l + (s) * 64;                                 \
        const __nv_bfloat16* s2_ = b_h + (s) * 64;                                 \
        const __nv_bfloat16* s3_ = b_l + (s) * 64;                                 \
        _Pragma("unroll")                                                          \
        for (int p = 0; p < 4; ++p) {                                              \
            int row = lrow + p * 32;                                               \
            uint32_t so = row * 128 + ((lc ^ (row & 7)) << 4);                     \
            CP_ASYNC16(smem_u32(dst_ + 0     + so), s0_ + (size_t)row * lda + lc * 8); \
            CP_ASYNC16(smem_u32(dst_ + 16384 + so), s1_ + (size_t)row * lda + lc * 8); \
            CP_ASYNC16(smem_u32(dst_ + 32768 + so), s2_ + (size_t)row * 1024 + lc * 8); \
            CP_ASYNC16(smem_u32(dst_ + 49152 + so), s3_ + (size_t)row * 1024 + lc * 8); \
        }                                                                          \
        CP_COMMIT();                                                               \
    } while (0)

    float cacc[4][4][4];
#pragma unroll
    for (int mi = 0; mi < 4; ++mi)
#pragma unroll
        for (int ni = 0; ni < 4; ++ni)
#pragma unroll
            for (int q = 0; q < 4; ++q) cacc[mi][ni][q] = 0.0f;

    LOAD_STAGE(0, 0);
    if (nstages > 1) LOAD_STAGE(1, 1);

#pragma unroll 1
    for (int s = 0; s < nstages; ++s) {
        if (s + 1 < nstages) { CP_WAIT1(); } else { CP_WAIT0(); }
        __syncthreads();

        const char* base = sm + (s % 3) * 65536;
#pragma unroll
        for (int j = 0; j < 4; ++j) {
            uint32_t aH[4][4], aL[4][4], bH[2][4], bL[2][4];
#pragma unroll
            for (int mi = 0; mi < 4; ++mi) {
                int row = wm * 64 + mi * 16 + (lane & 15);
                int ch  = 2 * j + (lane >> 4);
                uint32_t off = row * 128 + ((ch ^ (row & 7)) << 4);
                ldsm4(aH[mi], smem_u32(base + 0     + off));
                ldsm4(aL[mi], smem_u32(base + 16384 + off));
            }
#pragma unroll
            for (int pi = 0; pi < 2; ++pi) {
                int row = wn * 32 + pi * 16 + (lane & 7) + ((lane & 16) >> 1);
                int ch  = 2 * j + ((lane >> 3) & 1);
                uint32_t off = row * 128 + ((ch ^ (row & 7)) << 4);
                ldsm4(bH[pi], smem_u32(base + 32768 + off));
                ldsm4(bL[pi], smem_u32(base + 49152 + off));
            }
#pragma unroll
            for (int mi = 0; mi < 4; ++mi)
#pragma unroll
                for (int ni = 0; ni < 4; ++ni) {
                    uint32_t bh0 = bH[ni >> 1][(ni & 1) * 2];
                    uint32_t bh1 = bH[ni >> 1][(ni & 1) * 2 + 1];
                    uint32_t bl0 = bL[ni >> 1][(ni & 1) * 2];
                    uint32_t bl1 = bL[ni >> 1][(ni & 1) * 2 + 1];
                    mma16816(cacc[mi][ni], aH[mi], bh0, bh1);
                    mma16816(cacc[mi][ni], aH[mi], bl0, bl1);
                    mma16816(cacc[mi][ni], aL[mi], bh0, bh1);
                }
        }
        if (s + 2 < nstages) LOAD_STAGE((s + 2) % 3, s + 2);
    }

    float* cb = C + (size_t)kz * csplit_stride + (size_t)mt * 128 * N4_ + nt * 128;
#pragma unroll
    for (int mi = 0; mi < 4; ++mi)
#pragma unroll
        for (int ni = 0; ni < 4; ++ni) {
            int r   = wm * 64 + mi * 16 + (lane >> 2);
            int col = wn * 32 + ni * 8 + (lane & 3) * 2;
            *(float2*)(cb + (size_t)r * N4_ + col) =
                make_float2(cacc[mi][ni][0], cacc[mi][ni][1]);
            *(float2*)(cb + (size_t)(r + 8) * N4_ + col) =
                make_float2(cacc[mi][ni][2], cacc[mi][ni][3]);
        }
#undef LOAD_STAGE
}

// ---------------- persistent recurrence kernel (per-slab wavefront, polite spins) ----
// 128 CTAs x 512 threads. CTA = (nt 0..31, kz 0..3). Resident Wh slab (128KB),
// streamed h (3-buffer smem), per-nt producer flags gate each K64 slab, c in regs.
// Slab s of (nt,kz) reads h units [kz*256+s*64, +64) -> producer nts 8kz+2s, 8kz+2s+1.
#define PK_CTAS   128
#define PK_THREADS 512
#define SM_WHI(s)   (sm + (s) * 16384)
#define SM_WLO(s)   (sm + 65536 + (s) * 16384)
#define SM_HBUF(b)  (sm + 131072 + (b) * 32768)
#define PK_SMEM     (131072 + 3 * 32768)      // 229376

__global__ __launch_bounds__(PK_THREADS, 1)
void lstm_persistent(float* __restrict__ out)
{
    extern __shared__ __align__(128) char sm[];

    const int tid  = threadIdx.x;
    const int lane = tid & 31;
    const int wid  = tid >> 5;
    const int wm   = wid & 3;        // 4 warp-rows of 32 m
    const int wn   = wid >> 2;       // 4 warp-cols of 32 n
    const int cta  = blockIdx.x;
    const int nt   = cta & 31;
    const int kz   = cta >> 5;

    // eltwise ownership: rows kz*32 + b_r, unit-pair uh
    const int b_r = tid >> 4;
    const int uh  = tid & 15;
    const int gr  = kz * 32 + b_r;
    const int u0  = nt * 32 + uh * 2;

    float c0 = 0.0f, c1 = 0.0f;      // resident cell state

    // ---- resident W slab: 4 K64 sub-slabs, hi+lo ----
#pragma unroll
    for (int sub = 0; sub < 4; ++sub) {
#pragma unroll
        for (int i = 0; i < 4; ++i) {
            int c_ = tid + i * 512;
            int pl = c_ >> 10, rm = c_ & 1023, row = rm >> 3, c8 = rm & 7;
            const __nv_bfloat16* src = (pl ? g_whl : g_whh) +
                (size_t)(nt * 128 + row) * 1024 + kz * 256 + sub * 64 + c8 * 8;
            uint32_t so = row * 128 + ((c8 ^ (row & 7)) << 4);
            CP_ASYNC16(smem_u32((pl ? SM_WLO(sub) : SM_WHI(sub)) + so), src);
        }
    }
    CP_COMMIT();

#define LOADH(buf, s, rp) do {                                                      \
        char* dst_ = SM_HBUF(buf);                                                  \
        const __nv_bfloat16* hh_ = g_hh[rp];                                        \
        const __nv_bfloat16* hl_ = g_hl[rp];                                        \
        _Pragma("unroll")                                                           \
        for (int i = 0; i < 4; ++i) {                                               \
            int c_ = tid + i * 512;                                                 \
            int pl_ = c_ >> 10, rm_ = c_ & 1023, row_ = rm_ >> 3, c8_ = rm_ & 7;    \
            const __nv_bfloat16* src_ = (pl_ ? hl_ : hh_) +                         \
                (size_t)row_ * 1024 + kz * 256 + (s) * 64 + c8_ * 8;                \
            uint32_t so_ = pl_ * 16384 + row_ * 128 + ((c8_ ^ (row_ & 7)) << 4);    \
            CP_ASYNC16(smem_u32(dst_ + so_), src_);                                 \
        }                                                                           \
        CP_COMMIT();                                                                \
    } while (0)

#pragma unroll 1
    for (int t = 1; t < T_; ++t) {
        const unsigned htgt = 4u * (unsigned)(t - 1);
        const int rp = (t - 1) % 3;
        const int wp = t % 3;

        // prefetch this CTA's zx eltwise slice into L2 (HBM-resident buffer)
        {
            const float* pf = g_zx + (size_t)t * B_ * N4_
                              + (size_t)gr * N4_ + nt * 128 + uh * 8;
            asm volatile("prefetch.global.L2 [%0];" :: "l"(pf));
        }

        // gate + issue slabs 0 and 1 (producers: nts 8kz..8kz+3)
        WAIT_CNT(g_hnt, 8 * kz + 0, htgt);
        WAIT_CNT(g_hnt, 8 * kz + 1, htgt);
        __threadfence();
        LOADH(0, 0, rp);
        WAIT_CNT(g_hnt, 8 * kz + 2, htgt);
        WAIT_CNT(g_hnt, 8 * kz + 3, htgt);
        __threadfence();
        LOADH(1, 1, rp);

        float cacc[2][4][4];
#pragma unroll
        for (int mi = 0; mi < 2; ++mi)
#pragma unroll
            for (int ni = 0; ni < 4; ++ni)
#pragma unroll
                for (int q = 0; q < 4; ++q) cacc[mi][ni][q] = 0.0f;

#pragma unroll 1
        for (int s = 0; s < 4; ++s) {
            if (s < 3) { CP_WAIT1(); } else { CP_WAIT0(); }
            __syncthreads();

            const char* abase  = SM_HBUF(s % 3);
            const char* bhbase = SM_WHI(s);
            const char* blbase = SM_WLO(s);
#pragma unroll
            for (int j = 0; j < 4; ++j) {
                uint32_t aH[2][4], aL[2][4], bH[2][4], bL[2][4];
#pragma unroll
                for (int mi = 0; mi < 2; ++mi) {
                    int row = wm * 32 + mi * 16 + (lane & 15);
                    int ch  = 2 * j + (lane >> 4);
                    uint32_t off = row * 128 + ((ch ^ (row & 7)) << 4);
                    ldsm4(aH[mi], smem_u32(abase + off));
                    ldsm4(aL[mi], smem_u32(abase + 16384 + off));
                }
#pragma unroll
                for (int pi = 0; pi < 2; ++pi) {
                    int row = wn * 32 + pi * 16 + (lane & 7) + ((lane & 16) >> 1);
                    int ch  = 2 * j + ((lane >> 3) & 1);
                    uint32_t off = row * 128 + ((ch ^ (row & 7)) << 4);
                    ldsm4(bH[pi], smem_u32(bhbase + off));
                    ldsm4(bL[pi], smem_u32(blbase + off));
                }
#pragma unroll
                for (int mi = 0; mi < 2; ++mi)
#pragma unroll
                    for (int ni = 0; ni < 4; ++ni) {
                        uint32_t bh0 = bH[ni >> 1][(ni & 1) * 2];
                        uint32_t bh1 = bH[ni >> 1][(ni & 1) * 2 + 1];
                        uint32_t bl0 = bL[ni >> 1][(ni & 1) * 2];
                        uint32_t bl1 = bL[ni >> 1][(ni & 1) * 2 + 1];
                        mma16816(cacc[mi][ni], aH[mi], bh0, bh1);
                        mma16816(cacc[mi][ni], aH[mi], bl0, bl1);
                        mma16816(cacc[mi][ni], aL[mi], bh0, bh1);
                    }
            }
            if (s + 2 < 4) {
                // gate next slab's producers (wavefront: usually already done)
                WAIT_CNT(g_hnt, 8 * kz + 2 * (s + 2), htgt);
                WAIT_CNT(g_hnt, 8 * kz + 2 * (s + 2) + 1, htgt);
                __threadfence();
                LOADH((s + 2) % 3, s + 2, rp);
            }
        }

        // ---- protect zh slot: step t-1 readers (own nt group eltwise) must be done ----
        WAIT_CNT(g_hnt, nt, htgt);

        // ---- write z partials ----
        {
            float* cb = g_zh + (size_t)kz * (B_ * N4_) + nt * 128;
#pragma unroll
            for (int mi = 0; mi < 2; ++mi)
#pragma unroll
                for (int ni = 0; ni < 4; ++ni) {
                    int r   = wm * 32 + mi * 16 + (lane >> 2);
                    int col = wn * 32 + ni * 8 + (lane & 3) * 2;
                    *(float2*)(cb + (size_t)r * N4_ + col) =
                        make_float2(cacc[mi][ni][0], cacc[mi][ni][1]);
                    *(float2*)(cb + (size_t)(r + 8) * N4_ + col) =
                        make_float2(cacc[mi][ni][2], cacc[mi][ni][3]);
                }
        }
        __syncthreads();                           // all partial stores issued (CTA-wide)
        if (tid == 0) {
            __threadfence();                       // release partials
            atomicAdd(&g_pcnt[nt], 1u);
        }
        // polite wait for the 4 partials of this nt, then acquire
        WAIT_CNT(g_pcnt, nt, 4u * (unsigned)t);
        __threadfence();

        // ---- local eltwise: rows kz*32.., this nt's 32 units ----
        float hv0, hv1;
        {
            size_t rowoff = (size_t)gr * N4_ + nt * 128 + uh * 8;
            const float4* px = (const float4*)(g_zx + (size_t)t * B_ * N4_ + rowoff);
            float4 z0 = __ldg(px + 0);
            float4 z1 = __ldg(px + 1);
#pragma unroll
            for (int kzi = 0; kzi < NSPLIT; ++kzi) {
                const float4* pp = (const float4*)(g_zh + (size_t)kzi * (B_ * N4_) + rowoff);
                float4 a0 = __ldcg(pp + 0), a1 = __ldcg(pp + 1);
                z0.x += a0.x; z0.y += a0.y; z0.z += a0.z; z0.w += a0.w;
                z1.x += a1.x; z1.y += a1.y; z1.z += a1.z; z1.w += a1.w;
            }
            float4 bb0 = g_b4[u0];
            float4 bb1 = g_b4[u0 + 1];
            {
                float g  = ftanh(z0.x + bb0.x);
                float ii = fsig(z0.y + bb0.y);
                float f  = fsig(z0.z + bb0.z);
                float o  = fsig(z0.w + bb0.w);
                c0 = f * c0 + ii * g;
                hv0 = o * ftanh(c0);
            }
            {
                float g  = ftanh(z1.x + bb1.x);
                float ii = fsig(z1.y + bb1.y);
                float f  = fsig(z1.z + bb1.z);
                float o  = fsig(z1.w + bb1.w);
                c1 = f * c1 + ii * g;
                hv1 = o * ftanh(c1);
            }

            union { __nv_bfloat16 v[2]; uint32_t u; } hh, hl;
            __nv_bfloat16 h0 = __float2bfloat16(hv0);
            __nv_bfloat16 h1 = __float2bfloat16(hv1);
            hh.v[0] = h0; hh.v[1] = h1;
            hl.v[0] = __float2bfloat16(hv0 - __bfloat162float(h0));
            hl.v[1] = __float2bfloat16(hv1 - __bfloat162float(h1));
            *(uint32_t*)(g_hh[wp] + (size_t)gr * 1024 + u0) = hh.u;
            *(uint32_t*)(g_hl[wp] + (size_t)gr * 1024 + u0) = hl.u;
        }
        __syncthreads();
        if (tid == 0) {
            __threadfence();                       // release h planes
            atomicAdd(&g_hnt[nt], 1u);             // per-nt h ready
        }
        // out store off the critical path (device never reads out)
        *(float2*)(out + ((size_t)t * B_ + gr) * 1024 + u0) = make_float2(hv0, hv1);
    }
#undef LOADH
}

// ---------------- prep kernels ----------------
__global__ void split_plane(const float* __restrict__ src, __nv_bfloat16* __restrict__ hi,
                            __nv_bfloat16* __restrict__ lo, int n) {
    int i = blockIdx.x * blockDim.x + threadIdx.x;
    if (i < n) {
        float v = src[i];
        __nv_bfloat16 h = __float2bfloat16(v);
        hi[i] = h;
        lo[i] = __float2bfloat16(v - __bfloat162float(h));
    }
}

// gate-INTERLEAVED weight split: dest row = 4*unit + gate
__global__ void split_W(const float* __restrict__ Wg, const float* __restrict__ Wi,
                        const float* __restrict__ Wf, const float* __restrict__ Wo) {
    int idx = blockIdx.x * blockDim.x + threadIdx.x;
    if (idx >= 4 * 1024 * 2048) return;
    int gate = idx >> 21;
    int rem  = idx & ((1 << 21) - 1);
    int n    = rem >> 11;
    int k    = rem & 2047;
    const float* W = (gate == 0) ? Wg : (gate == 1) ? Wi : (gate == 2) ? Wf : Wo;
    float v = W[(size_t)n * 2048 + k];
    __nv_bfloat16 h = __float2bfloat16(v);
    __nv_bfloat16 l = __float2bfloat16(v - __bfloat162float(h));
    int gr = 4 * n + gate;
    if (k < 1024) {
        g_wxh[(size_t)gr * 1024 + k] = h;
        g_wxl[(size_t)gr * 1024 + k] = l;
    } else {
        g_whh[(size_t)gr * 1024 + (k - 1024)] = h;
        g_whl[(size_t)gr * 1024 + (k - 1024)] = l;
    }
}

__global__ void init_state(float* __restrict__ out,
                           const float* __restrict__ bg, const float* __restrict__ bi,
                           const float* __restrict__ bf, const float* __restrict__ bo) {
    int i = blockIdx.x * blockDim.x + threadIdx.x;
    if (i < BH_) {
        out[i] = 0.0f;                          // output[0] = h0 = 0
        g_hh[0][i] = __float2bfloat16(0.0f);    // h_0 planes (rp of t=1 is buffer 0)
        g_hl[0][i] = __float2bfloat16(0.0f);
    }
    if (i < H_) g_b4[i] = make_float4(bg[i], bi[i], bf[i], bo[i]);
    if (i < 32) { g_pcnt[i] = 0; g_hnt[i] = 0; }
}

// ---------------- launch ----------------
#define GEMM_SMEM (3 * 65536)

extern "C" void kernel_launch(void* const* d_in, const int* in_sizes, int n_in,
                              void* d_out, int out_size)
{
    const float* embeds = (const float*)d_in[0];
    const float* Wg = (const float*)d_in[1];
    const float* Wi = (const float*)d_in[2];
    const float* Wf = (const float*)d_in[3];
    const float* Wo = (const float*)d_in[4];
    const float* bg = (const float*)d_in[5];
    const float* bi = (const float*)d_in[6];
    const float* bf = (const float*)d_in[7];
    const float* bo = (const float*)d_in[8];
    float* out = (float*)d_out;

    cudaFuncSetAttribute(gemm_mma, cudaFuncAttributeMaxDynamicSharedMemorySize, GEMM_SMEM);
    cudaFuncSetAttribute(lstm_persistent, cudaFuncAttributeMaxDynamicSharedMemorySize, PK_SMEM);

    __nv_bfloat16 *p_eh, *p_el, *p_wxh, *p_wxl;
    float *p_zx;
    cudaGetSymbolAddress((void**)&p_eh,  g_eh);
    cudaGetSymbolAddress((void**)&p_el,  g_el);
    cudaGetSymbolAddress((void**)&p_wxh, g_wxh);
    cudaGetSymbolAddress((void**)&p_wxl, g_wxl);
    cudaGetSymbolAddress((void**)&p_zx,  g_zx);

    // prep
    {
        int n = T_ * B_ * E_;
        split_plane<<<(n + 255) / 256, 256>>>(embeds, p_eh, p_el, n);
    }
    split_W<<<(4 * 1024 * 2048 + 255) / 256, 256>>>(Wg, Wi, Wf, Wo);
    init_state<<<(BH_ + 255) / 256, 256>>>(out, bg, bi, bf, bo);

    // batch: Zx[t] = x_t @ Wx'^T for all t (interleaved cols)
    gemm_mma<<<dim3(32, 256, 1), 256, GEMM_SMEM>>>(p_eh, p_el, 1024, p_wxh, p_wxl,
                                                   p_zx, 0, 1024);

    // recurrence: one persistent kernel, per-slab wavefront flags (polite spins)
    lstm_persistent<<<PK_CTAS, PK_THREADS, PK_SMEM>>>(out);
}

// round 17
// speedup vs baseline: 2.5679x; 1.4418x over previous
#include <cuda_runtime.h>
#include <cuda_bf16.h>
#include <cstdint>

// ---------------- problem constants ----------------
#define T_    256
#define B_    128
#define E_    1024
#define H_    1024
#define N4_   4096
#define BH_   (B_ * H_)
#define NSPLIT 4

// ---------------- static device scratch ----------------
// weights / z use GATE-INTERLEAVED column order: col' = 4*unit + gate
__device__ float          g_zx[(size_t)T_ * B_ * N4_];   // x-part preactivations (interleaved)
__device__ float          g_zh[NSPLIT * B_ * N4_];       // per-step h-part partials
__device__ float4         g_b4[H_];                      // interleaved bias {bg,bi,bf,bo}[u]
__device__ __nv_bfloat16  g_eh[(size_t)T_ * B_ * E_];    // embeds hi
__device__ __nv_bfloat16  g_el[(size_t)T_ * B_ * E_];    // embeds lo
__device__ __nv_bfloat16  g_wxh[N4_ * 1024];             // Wx hi (interleaved rows, K-major)
__device__ __nv_bfloat16  g_wxl[N4_ * 1024];
__device__ __nv_bfloat16  g_whh[N4_ * 1024];             // Wh hi (interleaved rows)
__device__ __nv_bfloat16  g_whl[N4_ * 1024];
__device__ __nv_bfloat16  g_hh[3][BH_];                  // h triple buffer, hi plane
__device__ __nv_bfloat16  g_hl[3][BH_];                  // h triple buffer, lo plane
__device__ unsigned       g_hcnt[4];                     // per-region h-ready counters (monotonic)
__device__ unsigned       g_pcnt[32];                    // per-nt partial counters (monotonic)

// ---------------- arch-generic PTX helpers ----------------
__device__ __forceinline__ uint32_t smem_u32(const void* p) {
    uint32_t a;
    asm("{ .reg .u64 t; cvta.to.shared.u64 t, %1; cvt.u32.u64 %0, t; }" : "=r"(a) : "l"(p));
    return a;
}
__device__ __forceinline__ void ldsm4(uint32_t r[4], uint32_t saddr) {
    asm volatile("ldmatrix.sync.aligned.m8n8.x4.shared.b16 {%0,%1,%2,%3}, [%4];"
                 : "=r"(r[0]), "=r"(r[1]), "=r"(r[2]), "=r"(r[3]) : "r"(saddr));
}
__device__ __forceinline__ void mma16816(float c[4], const uint32_t a[4],
                                         uint32_t b0, uint32_t b1) {
    asm volatile("mma.sync.aligned.m16n8k16.row.col.f32.bf16.bf16.f32 "
                 "{%0,%1,%2,%3}, {%4,%5,%6,%7}, {%8,%9}, {%0,%1,%2,%3};"
                 : "+f"(c[0]), "+f"(c[1]), "+f"(c[2]), "+f"(c[3])
                 : "r"(a[0]), "r"(a[1]), "r"(a[2]), "r"(a[3]), "r"(b0), "r"(b1));
}
#define CP_ASYNC16(dst, src) \
    asm volatile("cp.async.cg.shared.global [%0], [%1], 16;" :: "r"(dst), "l"(src))
#define CP_COMMIT() asm volatile("cp.async.commit_group;" ::: "memory")
#define CP_WAIT0()  asm volatile("cp.async.wait_group 0;" ::: "memory")
#define CP_WAIT1()  asm volatile("cp.async.wait_group 1;" ::: "memory")

// fast sigmoid/tanh via MUFU exp (rel err ~1e-7; validated at rel_err 5.46e-6 in R12/R16)
__device__ __forceinline__ float fsig(float x)  { return 1.0f / (1.0f + __expf(-x)); }
__device__ __forceinline__ float ftanh(float x) { return 2.0f / (1.0f + __expf(-2.0f * x)) - 1.0f; }

// ---------------- batch 3-plane bf16 GEMM (3-stage pipeline, known-good) ----------------
__global__ __launch_bounds__(256, 1)
void gemm_mma(const __nv_bfloat16* __restrict__ Ah, const __nv_bfloat16* __restrict__ Al,
              int lda,
              const __nv_bfloat16* __restrict__ Bh, const __nv_bfloat16* __restrict__ Bl,
              float* __restrict__ C, size_t csplit_stride, int klen)
{
    extern __shared__ __align__(128) char sm[];

    const int tid  = threadIdx.x;
    const int lane = tid & 31;
    const int wid  = tid >> 5;
    const int wm   = wid & 1;
    const int wn   = wid >> 1;
    const int nt = blockIdx.x, mt = blockIdx.y, kz = blockIdx.z;
    const int kofs = kz * klen;
    const int nstages = klen >> 6;

    const __nv_bfloat16* a_h = Ah + (size_t)mt * 128 * lda + kofs;
    const __nv_bfloat16* a_l = Al + (size_t)mt * 128 * lda + kofs;
    const __nv_bfloat16* b_h = Bh + (size_t)nt * 128 * 1024 + kofs;
    const __nv_bfloat16* b_l = Bl + (size_t)nt * 128 * 1024 + kofs;

    const int lrow = tid >> 3;
    const int lc   = tid & 7;

#define LOAD_STAGE(buf, s) do {                                                    \
        char* dst_ = sm + (buf) * 65536;                                           \
        const __nv_bfloat16* s0_ = a_h + (s) * 64;                                 \
        const __nv_bfloat16* s1_ = a_l + (s) * 64;                                 \
        const __nv_bfloat16* s2_ = b_h + (s) * 64;                                 \
        const __nv_bfloat16* s3_ = b_l + (s) * 64;                                 \
        _Pragma("unroll")                                                          \
        for (int p = 0; p < 4; ++p) {                                              \
            int row = lrow + p * 32;                                               \
            uint32_t so = row * 128 + ((lc ^ (row & 7)) << 4);                     \
            CP_ASYNC16(smem_u32(dst_ + 0     + so), s0_ + (size_t)row * lda + lc * 8); \
            CP_ASYNC16(smem_u32(dst_ + 16384 + so), s1_ + (size_t)row * lda + lc * 8); \
            CP_ASYNC16(smem_u32(dst_ + 32768 + so), s2_ + (size_t)row * 1024 + lc * 8); \
            CP_ASYNC16(smem_u32(dst_ + 49152 + so), s3_ + (size_t)row * 1024 + lc * 8); \
        }                                                                          \
        CP_COMMIT();                                                               \
    } while (0)

    float cacc[4][4][4];
#pragma unroll
    for (int mi = 0; mi < 4; ++mi)
#pragma unroll
        for (int ni = 0; ni < 4; ++ni)
#pragma unroll
            for (int q = 0; q < 4; ++q) cacc[mi][ni][q] = 0.0f;

    LOAD_STAGE(0, 0);
    if (nstages > 1) LOAD_STAGE(1, 1);

#pragma unroll 1
    for (int s = 0; s < nstages; ++s) {
        if (s + 1 < nstages) { CP_WAIT1(); } else { CP_WAIT0(); }
        __syncthreads();

        const char* base = sm + (s % 3) * 65536;
#pragma unroll
        for (int j = 0; j < 4; ++j) {
            uint32_t aH[4][4], aL[4][4], bH[2][4], bL[2][4];
#pragma unroll
            for (int mi = 0; mi < 4; ++mi) {
                int row = wm * 64 + mi * 16 + (lane & 15);
                int ch  = 2 * j + (lane >> 4);
                uint32_t off = row * 128 + ((ch ^ (row & 7)) << 4);
                ldsm4(aH[mi], smem_u32(base + 0     + off));
                ldsm4(aL[mi], smem_u32(base + 16384 + off));
            }
#pragma unroll
            for (int pi = 0; pi < 2; ++pi) {
                int row = wn * 32 + pi * 16 + (lane & 7) + ((lane & 16) >> 1);
                int ch  = 2 * j + ((lane >> 3) & 1);
                uint32_t off = row * 128 + ((ch ^ (row & 7)) << 4);
                ldsm4(bH[pi], smem_u32(base + 32768 + off));
                ldsm4(bL[pi], smem_u32(base + 49152 + off));
            }
#pragma unroll
            for (int mi = 0; mi < 4; ++mi)
#pragma unroll
                for (int ni = 0; ni < 4; ++ni) {
                    uint32_t bh0 = bH[ni >> 1][(ni & 1) * 2];
                    uint32_t bh1 = bH[ni >> 1][(ni & 1) * 2 + 1];
                    uint32_t bl0 = bL[ni >> 1][(ni & 1) * 2];
                    uint32_t bl1 = bL[ni >> 1][(ni & 1) * 2 + 1];
                    mma16816(cacc[mi][ni], aH[mi], bh0, bh1);
                    mma16816(cacc[mi][ni], aH[mi], bl0, bl1);
                    mma16816(cacc[mi][ni], aL[mi], bh0, bh1);
                }
        }
        if (s + 2 < nstages) LOAD_STAGE((s + 2) % 3, s + 2);
    }

    float* cb = C + (size_t)kz * csplit_stride + (size_t)mt * 128 * N4_ + nt * 128;
#pragma unroll
    for (int mi = 0; mi < 4; ++mi)
#pragma unroll
        for (int ni = 0; ni < 4; ++ni) {
            int r   = wm * 64 + mi * 16 + (lane >> 2);
            int col = wn * 32 + ni * 8 + (lane & 3) * 2;
            *(float2*)(cb + (size_t)r * N4_ + col) =
                make_float2(cacc[mi][ni][0], cacc[mi][ni][1]);
            *(float2*)(cb + (size_t)(r + 8) * N4_ + col) =
                make_float2(cacc[mi][ni][2], cacc[mi][ni][3]);
        }
#undef LOAD_STAGE
}

// ---------------- persistent recurrence kernel (R11 region-flag scheme) ----------------
// 128 CTAs x 512 threads. CTA = (nt 0..31, kz 0..3). Resident Wh slab (128KB),
// streamed h (3-buffer smem), tid0-only spins/fences, c in registers.
// Region r covers h units produced by nt' in [8r, 8r+8). Consumer (nt,kz) waits
// region kz (its GEMM input) and region nt>>3 (protects its zh slot + h slot reuse).
#define PK_CTAS   128
#define PK_THREADS 512
#define SM_WHI(s)   (sm + (s) * 16384)
#define SM_WLO(s)   (sm + 65536 + (s) * 16384)
#define SM_HBUF(b)  (sm + 131072 + (b) * 32768)
#define PK_SMEM     (131072 + 3 * 32768)      // 229376

__global__ __launch_bounds__(PK_THREADS, 1)
void lstm_persistent(float* __restrict__ out)
{
    extern __shared__ __align__(128) char sm[];

    const int tid  = threadIdx.x;
    const int lane = tid & 31;
    const int wid  = tid >> 5;
    const int wm   = wid & 3;        // 4 warp-rows of 32 m
    const int wn   = wid >> 2;       // 4 warp-cols of 32 n
    const int cta  = blockIdx.x;
    const int nt   = cta & 31;
    const int kz   = cta >> 5;
    const int reg_own = nt >> 3;     // region this CTA's h output belongs to

    // eltwise ownership: rows kz*32 + b_r, unit-pair uh
    const int b_r = tid >> 4;
    const int uh  = tid & 15;
    const int gr  = kz * 32 + b_r;
    const int u0  = nt * 32 + uh * 2;

    float c0 = 0.0f, c1 = 0.0f;      // resident cell state

    // ---- resident W slab: 4 K64 sub-slabs, hi+lo ----
#pragma unroll
    for (int sub = 0; sub < 4; ++sub) {
#pragma unroll
        for (int i = 0; i < 4; ++i) {
            int c_ = tid + i * 512;
            int pl = c_ >> 10, rm = c_ & 1023, row = rm >> 3, c8 = rm & 7;
            const __nv_bfloat16* src = (pl ? g_whl : g_whh) +
                (size_t)(nt * 128 + row) * 1024 + kz * 256 + sub * 64 + c8 * 8;
            uint32_t so = row * 128 + ((c8 ^ (row & 7)) << 4);
            CP_ASYNC16(smem_u32((pl ? SM_WLO(sub) : SM_WHI(sub)) + so), src);
        }
    }
    CP_COMMIT();

#define LOADH(buf, s, rp) do {                                                      \
        char* dst_ = SM_HBUF(buf);                                                  \
        const __nv_bfloat16* hh_ = g_hh[rp];                                        \
        const __nv_bfloat16* hl_ = g_hl[rp];                                        \
        _Pragma("unroll")                                                           \
        for (int i = 0; i < 4; ++i) {                                               \
            int c_ = tid + i * 512;                                                 \
            int pl_ = c_ >> 10, rm_ = c_ & 1023, row_ = rm_ >> 3, c8_ = rm_ & 7;    \
            const __nv_bfloat16* src_ = (pl_ ? hl_ : hh_) +                         \
                (size_t)row_ * 1024 + kz * 256 + (s) * 64 + c8_ * 8;                \
            uint32_t so_ = pl_ * 16384 + row_ * 128 + ((c8_ ^ (row_ & 7)) << 4);    \
            CP_ASYNC16(smem_u32(dst_ + so_), src_);                                 \
        }                                                                           \
        CP_COMMIT();                                                                \
    } while (0)

#pragma unroll 1
    for (int t = 1; t < T_; ++t) {
        // prefetch this thread's zx eltwise slice into L2 (HBM-resident, cold)
        {
            const float* pf = g_zx + (size_t)t * B_ * N4_
                              + (size_t)gr * N4_ + nt * 128 + uh * 8;
            asm volatile("prefetch.global.L2 [%0];" :: "l"(pf));
        }

        // wait: region kz h-ready (GEMM input) + own region (slot-reuse safety)
        if (tid == 0) {
            unsigned tgt = 32u * (unsigned)(t - 1);
            while (*(volatile unsigned*)&g_hcnt[kz] < tgt) { }
            if (reg_own != kz)
                while (*(volatile unsigned*)&g_hcnt[reg_own] < tgt) { }
            __threadfence();     // acquire
        }
        __syncthreads();

        const int rp = (t - 1) % 3;
        const int wp = t % 3;

        LOADH(0, 0, rp);
        LOADH(1, 1, rp);

        float cacc[2][4][4];
#pragma unroll
        for (int mi = 0; mi < 2; ++mi)
#pragma unroll
            for (int ni = 0; ni < 4; ++ni)
#pragma unroll
                for (int q = 0; q < 4; ++q) cacc[mi][ni][q] = 0.0f;

#pragma unroll 1
        for (int s = 0; s < 4; ++s) {
            if (s < 3) { CP_WAIT1(); } else { CP_WAIT0(); }
            __syncthreads();

            const char* abase  = SM_HBUF(s % 3);
            const char* bhbase = SM_WHI(s);
            const char* blbase = SM_WLO(s);
#pragma unroll
            for (int j = 0; j < 4; ++j) {
                uint32_t aH[2][4], aL[2][4], bH[2][4], bL[2][4];
#pragma unroll
                for (int mi = 0; mi < 2; ++mi) {
                    int row = wm * 32 + mi * 16 + (lane & 15);
                    int ch  = 2 * j + (lane >> 4);
                    uint32_t off = row * 128 + ((ch ^ (row & 7)) << 4);
                    ldsm4(aH[mi], smem_u32(abase + off));
                    ldsm4(aL[mi], smem_u32(abase + 16384 + off));
                }
#pragma unroll
                for (int pi = 0; pi < 2; ++pi) {
                    int row = wn * 32 + pi * 16 + (lane & 7) + ((lane & 16) >> 1);
                    int ch  = 2 * j + ((lane >> 3) & 1);
                    uint32_t off = row * 128 + ((ch ^ (row & 7)) << 4);
                    ldsm4(bH[pi], smem_u32(bhbase + off));
                    ldsm4(bL[pi], smem_u32(blbase + off));
                }
#pragma unroll
                for (int mi = 0; mi < 2; ++mi)
#pragma unroll
                    for (int ni = 0; ni < 4; ++ni) {
                        uint32_t bh0 = bH[ni >> 1][(ni & 1) * 2];
                        uint32_t bh1 = bH[ni >> 1][(ni & 1) * 2 + 1];
                        uint32_t bl0 = bL[ni >> 1][(ni & 1) * 2];
                        uint32_t bl1 = bL[ni >> 1][(ni & 1) * 2 + 1];
                        mma16816(cacc[mi][ni], aH[mi], bh0, bh1);
                        mma16816(cacc[mi][ni], aH[mi], bl0, bl1);
                        mma16816(cacc[mi][ni], aL[mi], bh0, bh1);
                    }
            }
            if (s + 2 < 4) LOADH((s + 2) % 3, s + 2, rp);
        }

        // ---- write z partials ----
        {
            float* cb = g_zh + (size_t)kz * (B_ * N4_) + nt * 128;
#pragma unroll
            for (int mi = 0; mi < 2; ++mi)
#pragma unroll
                for (int ni = 0; ni < 4; ++ni) {
                    int r   = wm * 32 + mi * 16 + (lane >> 2);
                    int col = wn * 32 + ni * 8 + (lane & 3) * 2;
                    *(float2*)(cb + (size_t)r * N4_ + col) =
                        make_float2(cacc[mi][ni][0], cacc[mi][ni][1]);
                    *(float2*)(cb + (size_t)(r + 8) * N4_ + col) =
                        make_float2(cacc[mi][ni][2], cacc[mi][ni][3]);
                }
        }
        __syncthreads();
        if (tid == 0) {
            __threadfence();                       // release partials
            atomicAdd(&g_pcnt[nt], 1u);
            unsigned tgt = 4u * (unsigned)t;
            while (*(volatile unsigned*)&g_pcnt[nt] < tgt) { }
            __threadfence();                       // acquire partners' partials
        }
        __syncthreads();

        // ---- local eltwise: rows kz*32.., this nt's 32 units ----
        float hv0, hv1;
        {
            size_t rowoff = (size_t)gr * N4_ + nt * 128 + uh * 8;
            const float4* px = (const float4*)(g_zx + (size_t)t * B_ * N4_ + rowoff);
            float4 z0 = __ldg(px + 0);
            float4 z1 = __ldg(px + 1);
#pragma unroll
            for (int kzi = 0; kzi < NSPLIT; ++kzi) {
                const float4* pp = (const float4*)(g_zh + (size_t)kzi * (B_ * N4_) + rowoff);
                float4 a0 = __ldcg(pp + 0), a1 = __ldcg(pp + 1);
                z0.x += a0.x; z0.y += a0.y; z0.z += a0.z; z0.w += a0.w;
                z1.x += a1.x; z1.y += a1.y; z1.z += a1.z; z1.w += a1.w;
            }
            float4 bb0 = g_b4[u0];
            float4 bb1 = g_b4[u0 + 1];
            {
                float g  = ftanh(z0.x + bb0.x);
                float ii = fsig(z0.y + bb0.y);
                float f  = fsig(z0.z + bb0.z);
                float o  = fsig(z0.w + bb0.w);
                c0 = f * c0 + ii * g;
                hv0 = o * ftanh(c0);
            }
            {
                float g  = ftanh(z1.x + bb1.x);
                float ii = fsig(z1.y + bb1.y);
                float f  = fsig(z1.z + bb1.z);
                float o  = fsig(z1.w + bb1.w);
                c1 = f * c1 + ii * g;
                hv1 = o * ftanh(c1);
            }

            union { __nv_bfloat16 v[2]; uint32_t u; } hh, hl;
            __nv_bfloat16 h0 = __float2bfloat16(hv0);
            __nv_bfloat16 h1 = __float2bfloat16(hv1);
            hh.v[0] = h0; hh.v[1] = h1;
            hl.v[0] = __float2bfloat16(hv0 - __bfloat162float(h0));
            hl.v[1] = __float2bfloat16(hv1 - __bfloat162float(h1));
            *(uint32_t*)(g_hh[wp] + (size_t)gr * 1024 + u0) = hh.u;
            *(uint32_t*)(g_hl[wp] + (size_t)gr * 1024 + u0) = hl.u;
        }
        __syncthreads();
        if (tid == 0) {
            __threadfence();                       // release h planes
            atomicAdd(&g_hcnt[reg_own], 1u);       // h region ready
        }
        // out store off the critical path (device never reads out)
        *(float2*)(out + ((size_t)t * B_ + gr) * 1024 + u0) = make_float2(hv0, hv1);
    }
#undef LOADH
}

// ---------------- prep kernels ----------------
__global__ void split_plane(const float* __restrict__ src, __nv_bfloat16* __restrict__ hi,
                            __nv_bfloat16* __restrict__ lo, int n) {
    int i = blockIdx.x * blockDim.x + threadIdx.x;
    if (i < n) {
        float v = src[i];
        __nv_bfloat16 h = __float2bfloat16(v);
        hi[i] = h;
        lo[i] = __float2bfloat16(v - __bfloat162float(h));
    }
}

// gate-INTERLEAVED weight split: dest row = 4*unit + gate
__global__ void split_W(const float* __restrict__ Wg, const float* __restrict__ Wi,
                        const float* __restrict__ Wf, const float* __restrict__ Wo) {
    int idx = blockIdx.x * blockDim.x + threadIdx.x;
    if (idx >= 4 * 1024 * 2048) return;
    int gate = idx >> 21;
    int rem  = idx & ((1 << 21) - 1);
    int n    = rem >> 11;
    int k    = rem & 2047;
    const float* W = (gate == 0) ? Wg : (gate == 1) ? Wi : (gate == 2) ? Wf : Wo;
    float v = W[(size_t)n * 2048 + k];
    __nv_bfloat16 h = __float2bfloat16(v);
    __nv_bfloat16 l = __float2bfloat16(v - __bfloat162float(h));
    int gr = 4 * n + gate;
    if (k < 1024) {
        g_wxh[(size_t)gr * 1024 + k] = h;
        g_wxl[(size_t)gr * 1024 + k] = l;
    } else {
        g_whh[(size_t)gr * 1024 + (k - 1024)] = h;
        g_whl[(size_t)gr * 1024 + (k - 1024)] = l;
    }
}

__global__ void init_state(float* __restrict__ out,
                           const float* __restrict__ bg, const float* __restrict__ bi,
                           const float* __restrict__ bf, const float* __restrict__ bo) {
    int i = blockIdx.x * blockDim.x + threadIdx.x;
    if (i < BH_) {
        out[i] = 0.0f;                          // output[0] = h0 = 0
        g_hh[0][i] = __float2bfloat16(0.0f);    // h_0 planes (rp of t=1 is buffer 0)
        g_hl[0][i] = __float2bfloat16(0.0f);
    }
    if (i < H_) g_b4[i] = make_float4(bg[i], bi[i], bf[i], bo[i]);
    if (i < 32) g_pcnt[i] = 0;
    if (i < 4)  g_hcnt[i] = 0;
}

// ---------------- launch ----------------
#define GEMM_SMEM (3 * 65536)

extern "C" void kernel_launch(void* const* d_in, const int* in_sizes, int n_in,
                              void* d_out, int out_size)
{
    const float* embeds = (const float*)d_in[0];
    const float* Wg = (const float*)d_in[1];
    const float* Wi = (const float*)d_in[2];
    const float* Wf = (const float*)d_in[3];
    const float* Wo = (const float*)d_in[4];
    const float* bg = (const float*)d_in[5];
    const float* bi = (const float*)d_in[6];
    const float* bf = (const float*)d_in[7];
    const float* bo = (const float*)d_in[8];
    float* out = (float*)d_out;

    cudaFuncSetAttribute(gemm_mma, cudaFuncAttributeMaxDynamicSharedMemorySize, GEMM_SMEM);
    cudaFuncSetAttribute(lstm_persistent, cudaFuncAttributeMaxDynamicSharedMemorySize, PK_SMEM);

    __nv_bfloat16 *p_eh, *p_el, *p_wxh, *p_wxl;
    float *p_zx;
    cudaGetSymbolAddress((void**)&p_eh,  g_eh);
    cudaGetSymbolAddress((void**)&p_el,  g_el);
    cudaGetSymbolAddress((void**)&p_wxh, g_wxh);
    cudaGetSymbolAddress((void**)&p_wxl, g_wxl);
    cudaGetSymbolAddress((void**)&p_zx,  g_zx);

    // prep
    {
        int n = T_ * B_ * E_;
        split_plane<<<(n + 255) / 256, 256>>>(embeds, p_eh, p_el, n);
    }
    split_W<<<(4 * 1024 * 2048 + 255) / 256, 256>>>(Wg, Wi, Wf, Wo);
    init_state<<<(BH_ + 255) / 256, 256>>>(out, bg, bi, bf, bo);

    // batch: Zx[t] = x_t @ Wx'^T for all t (interleaved cols)
    gemm_mma<<<dim3(32, 256, 1), 256, GEMM_SMEM>>>(p_eh, p_el, 1024, p_wxh, p_wxl,
                                                   p_zx, 0, 1024);

    // recurrence: one persistent kernel, R11 region-flag scheme
    lstm_persistent<<<PK_CTAS, PK_THREADS, PK_SMEM>>>(out);
}